// round 15
// baseline (speedup 1.0000x reference)
#include <cuda_runtime.h>
#include <cuda_fp16.h>
#include <math.h>

// Problem constants
#define Bc   4
#define Lc   16384
#define Dc   128
#define DIc  256
#define DSc  16
#define DTRc 8
#define Kc   4
#define Nc   (Bc*Lc)
#define NCH  256
#define Tc   (Lc/NCH)      // 64
#define EPSc 1e-5f

typedef unsigned int       u32;
typedef unsigned short     u16;

// ---------------- scratch (device globals; no allocations) ----------------
__device__ __half  g_xi [Nc*DIc];
__device__ __half  g_z  [Nc*DIc];
__device__ __half  g_xc [Nc*DIc];
__device__ __half  g_y  [Nc*DIc];
__device__ u32     g_dtx[Nc*DIc];     // lo16: u=dt*xc fp16, hi16: e1=exp(dt*a0) fixed *65535
__device__ float   g_dbc[Nc*40];
__device__ float   g_ch [Bc*NCH*DIc*DSc];
__device__ float   g_sdt[Bc*NCH*DIc];
__device__ float   g_hin[Bc*NCH*DIc*DSc];
// fp16 hi/lo split weights, natural [k][n] orientation
__device__ __half g_win_h [128*512], g_win_l [128*512];
__device__ __half g_wout_h[256*128], g_wout_l[256*128];
__device__ __half g_wxp_h [256*64],  g_wxp_l [256*64];

// ---------------- helpers ----------------
__device__ __forceinline__ u32 smem_u32(const void* p) {
    u32 a;
    asm("{ .reg .u64 t; cvta.to.shared.u64 t, %1; cvt.u32.u64 %0, t; }"
        : "=r"(a) : "l"(p));
    return a;
}
__device__ __forceinline__ u32 f2h2(float x, float y) {
    __half2 t = __floats2half2_rn(x, y);
    return *(u32*)&t;
}
#define LDSM4(r, a) \
    asm volatile("ldmatrix.sync.aligned.m8n8.x4.shared.b16 {%0,%1,%2,%3}, [%4];" \
        : "=r"((r)[0]),"=r"((r)[1]),"=r"((r)[2]),"=r"((r)[3]) : "r"(a))
#define LDSM4T(r, a) \
    asm volatile("ldmatrix.sync.aligned.m8n8.x4.trans.shared.b16 {%0,%1,%2,%3}, [%4];" \
        : "=r"((r)[0]),"=r"((r)[1]),"=r"((r)[2]),"=r"((r)[3]) : "r"(a))
#define MMA(c, a, b) \
    asm volatile("mma.sync.aligned.m16n8k16.row.col.f32.f16.f16.f32 " \
        "{%0,%1,%2,%3}, {%4,%5,%6,%7}, {%8,%9}, {%0,%1,%2,%3};" \
        : "+f"((c)[0]),"+f"((c)[1]),"+f"((c)[2]),"+f"((c)[3]) \
        : "r"((a)[0]),"r"((a)[1]),"r"((a)[2]),"r"((a)[3]),"r"((b)[0]),"r"((b)[1]))

#define LDA 136   // smem row stride in halves (272B -> conflict-free ldmatrix)
#define LDB2 72   // x_proj B stride (144B -> conflict-free)

// =====================================================================
// K0: weight prep — fp16 hi/lo split
// =====================================================================
__global__ __launch_bounds__(256) void k_prep(
    const float* __restrict__ inw, const float* __restrict__ outw,
    const float* __restrict__ xpw)
{
    int idx = blockIdx.x*256 + threadIdx.x;
    float v; __half* dh; __half* dl; int slot;
    if (idx < 128*512) {
        v = inw[idx]; dh = g_win_h; dl = g_win_l; slot = idx;
    } else if (idx < 128*512 + 256*128) {
        int i = idx - 128*512;
        v = outw[i]; dh = g_wout_h; dl = g_wout_l; slot = i;
    } else if (idx < 128*512 + 256*128 + 256*64) {
        int i = idx - 128*512 - 256*128;
        int k = i >> 6, n = i & 63;
        v = (n < 40) ? xpw[k*40 + n] : 0.f;
        dh = g_wxp_h; dl = g_wxp_l; slot = i;
    } else return;
    __half h = __float2half_rn(v);
    dh[slot] = h;
    dl[slot] = __float2half_rn(v - __half2float(h));
}

// =====================================================================
// K1: fused embed + gather + RMSNorm + in_proj (fp16 HMMA, M128, N512, K128)
// =====================================================================
__global__ __launch_bounds__(256) void k_in(
    const float* __restrict__ feats, const int* __restrict__ coords,
    const float* __restrict__ pos_w, const float* __restrict__ pos_b,
    const float* __restrict__ rms_w, const int* __restrict__ perm)
{
    extern __shared__ __half sm[];
    __half *A = sm, *Bh = sm + 128*LDA, *Bl = Bh + 64*LDA;
    const u32 A_u = smem_u32(A), Bh_u = smem_u32(Bh), Bl_u = smem_u32(Bl);
    const int tid = threadIdx.x, lane = tid & 31, wid = tid >> 5;
    const int m0 = blockIdx.x * 128;
    const int wm = wid >> 1, wn = wid & 1;

    for (int r = wid; r < 128; r += 8) {
        int m   = m0 + r;
        int src = (m & ~(Lc-1)) + perm[m];
        float c0 = (float)coords[src*3+0];
        float c1 = (float)coords[src*3+1];
        float c2 = (float)coords[src*3+2];
        int c = lane*4;
        float4 f = *(const float4*)(feats + (size_t)src*Dc + c);
        float v[4]; float ss = 0.f;
        #pragma unroll
        for (int j = 0; j < 4; ++j) {
            v[j] = (&f.x)[j] + c0*pos_w[c+j] + c1*pos_w[Dc+c+j]
                   + c2*pos_w[2*Dc+c+j] + pos_b[c+j];
            ss += v[j]*v[j];
        }
        #pragma unroll
        for (int o = 16; o > 0; o >>= 1) ss += __shfl_xor_sync(0xffffffffu, ss, o);
        float rs = rsqrtf(ss*(1.f/Dc) + EPSc);
        int base = r*LDA + c;
        *(u32*)&A[base]   = f2h2(v[0]*rs*rms_w[c+0], v[1]*rs*rms_w[c+1]);
        *(u32*)&A[base+2] = f2h2(v[2]*rs*rms_w[c+2], v[3]*rs*rms_w[c+3]);
    }
    __syncthreads();

    for (int nb = 0; nb < 4; ++nb) {
        float acc[2][8][4] = {};
        for (int kb = 0; kb < 2; ++kb) {
            for (int i = tid; i < 64*64; i += 256) {
                int k = i >> 6, p = i & 63;
                *(u32*)&Bh[k*LDA + 2*p] = ((const u32*)g_win_h)[(kb*64+k)*256 + nb*64 + p];
                *(u32*)&Bl[k*LDA + 2*p] = ((const u32*)g_win_l)[(kb*64+k)*256 + nb*64 + p];
            }
            __syncthreads();
            #pragma unroll
            for (int k0 = 0; k0 < 64; k0 += 16) {
                u32 a[2][4];
                #pragma unroll
                for (int mf = 0; mf < 2; ++mf)
                    LDSM4(a[mf], A_u + (u32)(((wm*32 + mf*16 + (lane & 15))*LDA
                                              + kb*64 + k0 + (lane >> 4)*8) * 2));
                #pragma unroll
                for (int pass = 0; pass < 2; ++pass) {
                    u32 B_u = pass ? Bl_u : Bh_u;
                    u32 b[8][2];
                    #pragma unroll
                    for (int nf2 = 0; nf2 < 4; ++nf2) {
                        u32 bb[4];
                        LDSM4T(bb, B_u + (u32)(((k0 + (lane & 15))*LDA
                                                + wn*64 + nf2*16 + (lane >> 4)*8) * 2));
                        b[2*nf2+0][0] = bb[0]; b[2*nf2+0][1] = bb[1];
                        b[2*nf2+1][0] = bb[2]; b[2*nf2+1][1] = bb[3];
                    }
                    #pragma unroll
                    for (int mf = 0; mf < 2; ++mf)
                        #pragma unroll
                        for (int nf = 0; nf < 8; ++nf)
                            MMA(acc[mf][nf], a[mf], b[nf]);
                }
            }
            __syncthreads();
        }
        __half* dst = (nb < 2) ? g_xi : g_z;
        int nbase = (nb & 1)*128 + wn*64;
        #pragma unroll
        for (int mf = 0; mf < 2; ++mf) {
            int r0 = m0 + wm*32 + mf*16 + (lane >> 2);
            #pragma unroll
            for (int nf = 0; nf < 8; ++nf) {
                int ncol = nbase + nf*8 + (lane & 3)*2;
                *(u32*)&dst[(size_t)r0*DIc + ncol]     = f2h2(acc[mf][nf][0], acc[mf][nf][1]);
                *(u32*)&dst[(size_t)(r0+8)*DIc + ncol] = f2h2(acc[mf][nf][2], acc[mf][nf][3]);
            }
        }
    }
}

// =====================================================================
// K2: fused conv+silu + x_proj (fp16 HMMA, M128, N=64(pad of 40), K=256)
// =====================================================================
__global__ __launch_bounds__(256) void k_xp(
    const float* __restrict__ cw, const float* __restrict__ cb)
{
    extern __shared__ __half sm[];
    __half *A = sm, *Bh = sm + 128*LDA, *Bl = Bh + 128*LDB2;
    const u32 A_u = smem_u32(A), Bh_u = smem_u32(Bh), Bl_u = smem_u32(Bl);
    const int tid = threadIdx.x, lane = tid & 31, wid = tid >> 5;
    const int m0 = blockIdx.x * 128;
    const int wm = wid >> 1, wn = wid & 1;

    float acc[2][4][4] = {};
    for (int kc = 0; kc < 2; ++kc) {
        int kk = kc*128;
        for (int i = tid; i < 128*64; i += 256) {
            int r = i >> 6, p = i & 63;
            int col = kk + 2*p;
            int m = m0 + r;
            float ax = cb[col], ay = cb[col+1];
            #pragma unroll
            for (int j = 0; j < Kc; ++j) {
                if (((m & (Lc-1)) - 3 + j) >= 0) {
                    __half2 xv = *(const __half2*)(g_xi + (size_t)(m-3+j)*DIc + col);
                    float2 xf = __half22float2(xv);
                    ax += xf.x * cw[col*Kc + j];
                    ay += xf.y * cw[(col+1)*Kc + j];
                }
            }
            ax = ax / (1.f + __expf(-ax));
            ay = ay / (1.f + __expf(-ay));
            u32 pk = f2h2(ax, ay);
            *(u32*)(g_xc + (size_t)m*DIc + col) = pk;
            *(u32*)&A[r*LDA + 2*p] = pk;
        }
        for (int i = tid; i < 128*32; i += 256) {
            int k = i >> 5, p = i & 31;
            *(u32*)&Bh[k*LDB2 + 2*p] = ((const u32*)g_wxp_h)[(kk+k)*32 + p];
            *(u32*)&Bl[k*LDB2 + 2*p] = ((const u32*)g_wxp_l)[(kk+k)*32 + p];
        }
        __syncthreads();

        #pragma unroll
        for (int k0 = 0; k0 < 128; k0 += 16) {
            u32 a[2][4];
            #pragma unroll
            for (int mf = 0; mf < 2; ++mf)
                LDSM4(a[mf], A_u + (u32)(((wm*32 + mf*16 + (lane & 15))*LDA
                                          + k0 + (lane >> 4)*8) * 2));
            #pragma unroll
            for (int pass = 0; pass < 2; ++pass) {
                u32 B_u = pass ? Bl_u : Bh_u;
                u32 b[4][2];
                #pragma unroll
                for (int nf2 = 0; nf2 < 2; ++nf2) {
                    u32 bb[4];
                    LDSM4T(bb, B_u + (u32)(((k0 + (lane & 15))*LDB2
                                            + wn*32 + nf2*16 + (lane >> 4)*8) * 2));
                    b[2*nf2+0][0] = bb[0]; b[2*nf2+0][1] = bb[1];
                    b[2*nf2+1][0] = bb[2]; b[2*nf2+1][1] = bb[3];
                }
                #pragma unroll
                for (int mf = 0; mf < 2; ++mf)
                    #pragma unroll
                    for (int nf = 0; nf < 4; ++nf)
                        MMA(acc[mf][nf], a[mf], b[nf]);
            }
        }
        __syncthreads();
    }

    #pragma unroll
    for (int mf = 0; mf < 2; ++mf) {
        int r0 = m0 + wm*32 + mf*16 + (lane >> 2);
        #pragma unroll
        for (int nf = 0; nf < 4; ++nf) {
            int ncol = wn*32 + nf*8 + (lane & 3)*2;
            if (ncol < 40) {
                *(float2*)&g_dbc[(size_t)r0*40 + ncol]     = make_float2(acc[mf][nf][0], acc[mf][nf][1]);
                *(float2*)&g_dbc[(size_t)(r0+8)*40 + ncol] = make_float2(acc[mf][nf][2], acc[mf][nf][3]);
            }
        }
    }
}

// =====================================================================
// K3: dt = softplus(dt8 @ dt_proj_w + b); packs (u=dt*xc fp16, e1 fixed16)
//     into g_dtx; per-chunk sum(dt) fp32
// =====================================================================
__global__ __launch_bounds__(256) void k_dt(
    const float* __restrict__ dtw, const float* __restrict__ dtb,
    const float* __restrict__ A_log)
{
    __shared__ float dr[Tc][8];
    int blk = blockIdx.x;          // = b*NCH + ch
    int m0 = blk*Tc;
    int tid = threadIdx.x;
    { int t = tid >> 2, k2 = (tid & 3)*2;
      *(float2*)&dr[t][k2] = *(const float2*)&g_dbc[(size_t)(m0+t)*40 + k2]; }
    __syncthreads();
    float wr[8];
    #pragma unroll
    for (int k = 0; k < 8; ++k) wr[k] = dtw[k*DIc + tid];
    float b = dtb[tid];
    float a0 = -__expf(A_log[tid*DSc]);
    float sdt = 0.f;
    #pragma unroll 2
    for (int t = 0; t < Tc; ++t) {
        float v = b;
        #pragma unroll
        for (int k = 0; k < 8; ++k) v += dr[t][k]*wr[k];
        float sp = (v > 15.f) ? v : __logf(1.f + __expf(v));
        sdt += sp;
        float xcv = __half2float(g_xc[(size_t)(m0+t)*DIc + tid]);
        float uu  = sp * xcv;
        float e1f = __expf(sp * a0);               // in (0,1]
        u32 pk = (u32)__half_as_ushort(__float2half_rn(uu))
               | ((u32)(int)(e1f*65535.f + 0.5f) << 16);
        g_dtx[(size_t)(m0+t)*DIc + tid] = pk;
    }
    g_sdt[(size_t)blk*DIc + tid] = sdt;
}

// ---------------- power tree: pw[s] = e1^(s+1), depth ~3 ----------------
#define POWER_TREE(pw, e1) do { \
    float _e2 = (e1)*(e1), _e4 = _e2*_e2, _e8 = _e4*_e4; \
    pw[0]=(e1); pw[1]=_e2; pw[2]=_e2*(e1); pw[3]=_e4; \
    pw[4]=_e4*(e1); pw[5]=_e4*_e2; pw[6]=_e4*pw[2]; pw[7]=_e8; \
    pw[8]=_e8*(e1); pw[9]=_e8*_e2; pw[10]=_e8*pw[2]; pw[11]=_e8*_e4; \
    pw[12]=_e8*pw[4]; pw[13]=_e8*pw[5]; pw[14]=_e8*pw[6]; pw[15]=_e8*_e8; \
} while (0)

#define UNPACK_DTX(pk, u, e1) do { \
    (u)  = __half2float(__ushort_as_half((u16)((pk) & 0xFFFFu))); \
    (e1) = (float)((pk) >> 16) * (1.f/65535.f); \
} while (0)

// =====================================================================
// K4: scan pass 1 — per-chunk final state; NO MUFU in the hot loop
// =====================================================================
__global__ __launch_bounds__(256) void k_scan1(const float* __restrict__ A_log)
{
    __shared__ float4 Bsh4[Tc*4];
    float* Bshf = (float*)Bsh4;
    int blk = blockIdx.x;
    int base = blk*Tc;
    int tid = threadIdx.x, lane = tid & 31, wid = tid >> 5;
    for (int t = wid; t < Tc; t += 8)
        if (lane < 16) Bshf[t*16 + lane] = g_dbc[(size_t)(base+t)*40 + 8 + lane];
    __syncthreads();
    int d = tid;
    float a0 = -__expf(A_log[d*DSc]);
    bool uni = true;
    #pragma unroll
    for (int s = 1; s < DSc; ++s) {
        float as = -__expf(A_log[d*DSc+s]);
        uni = uni && (fabsf(as - (float)(s+1)*a0) <= 1e-4f*fabsf((float)(s+1)*a0) + 1e-6f);
    }
    float h[DSc];
    #pragma unroll
    for (int s = 0; s < DSc; ++s) h[s] = 0.f;
    if (uni) {
        #pragma unroll 4
        for (int t = 0; t < Tc; ++t) {
            u32 pk = g_dtx[(size_t)(base+t)*DIc + d];
            float u, e1; UNPACK_DTX(pk, u, e1);
            float pw[16]; POWER_TREE(pw, e1);
            float4 B0 = Bsh4[t*4+0], B1 = Bsh4[t*4+1], B2 = Bsh4[t*4+2], B3 = Bsh4[t*4+3];
            h[0]  = fmaf(pw[0],  h[0],  u*B0.x);
            h[1]  = fmaf(pw[1],  h[1],  u*B0.y);
            h[2]  = fmaf(pw[2],  h[2],  u*B0.z);
            h[3]  = fmaf(pw[3],  h[3],  u*B0.w);
            h[4]  = fmaf(pw[4],  h[4],  u*B1.x);
            h[5]  = fmaf(pw[5],  h[5],  u*B1.y);
            h[6]  = fmaf(pw[6],  h[6],  u*B1.z);
            h[7]  = fmaf(pw[7],  h[7],  u*B1.w);
            h[8]  = fmaf(pw[8],  h[8],  u*B2.x);
            h[9]  = fmaf(pw[9],  h[9],  u*B2.y);
            h[10] = fmaf(pw[10], h[10], u*B2.z);
            h[11] = fmaf(pw[11], h[11], u*B2.w);
            h[12] = fmaf(pw[12], h[12], u*B3.x);
            h[13] = fmaf(pw[13], h[13], u*B3.y);
            h[14] = fmaf(pw[14], h[14], u*B3.z);
            h[15] = fmaf(pw[15], h[15], u*B3.w);
        }
    } else {
        #pragma unroll 2
        for (int t = 0; t < Tc; ++t) {
            u32 pk = g_dtx[(size_t)(base+t)*DIc + d];
            float u, e1; UNPACK_DTX(pk, u, e1);
            float le = __logf(fmaxf(e1, 1e-30f));     // = dt*a0
            #pragma unroll
            for (int s = 0; s < DSc; ++s) {
                float as = -__expf(A_log[d*DSc+s]);
                h[s] = __expf(le*(as/a0))*h[s] + u*Bshf[t*16+s];
            }
        }
    }
    size_t co = ((size_t)blk*DIc + d)*DSc;
    #pragma unroll
    for (int s = 0; s < DSc; ++s) g_ch[co+s] = h[s];
}

// =====================================================================
// K5: chunk combine — warp-parallel affine scan (one warp per (b,d,s))
// =====================================================================
__global__ __launch_bounds__(256) void k_comb(const float* __restrict__ A_log)
{
    int sid = blockIdx.x*8 + (threadIdx.x >> 5);   // series id < 16384
    int lane = threadIdx.x & 31;
    int b = sid >> 12;
    int d = (sid >> 4) & (DIc-1);
    int s = sid & 15;
    float a = -__expf(A_log[d*DSc + s]);

    float dec[8], cv[8];
    int ch0 = lane*8;
    #pragma unroll
    for (int j = 0; j < 8; ++j) {
        int ch = ch0 + j;
        cv[j]  = g_ch[((size_t)(b*NCH+ch)*DIc + d)*DSc + s];
        dec[j] = __expf(a * g_sdt[(size_t)(b*NCH+ch)*DIc + d]);
    }
    float P = 1.f, S = 0.f;
    #pragma unroll
    for (int j = 0; j < 8; ++j) { S = dec[j]*S + cv[j]; P *= dec[j]; }
    #pragma unroll
    for (int o = 1; o < 32; o <<= 1) {
        float Pp = __shfl_up_sync(0xffffffffu, P, o);
        float Sp = __shfl_up_sync(0xffffffffu, S, o);
        if (lane >= o) { S = fmaf(P, Sp, S); P *= Pp; }
    }
    float H = __shfl_up_sync(0xffffffffu, S, 1);
    if (lane == 0) H = 0.f;
    #pragma unroll
    for (int j = 0; j < 8; ++j) {
        int ch = ch0 + j;
        g_hin[((size_t)(b*NCH+ch)*DIc + d)*DSc + s] = H;
        H = dec[j]*H + cv[j];
    }
}

// =====================================================================
// K6: scan pass 2 — replay with carry-in + fused +xc*D and *silu(z)
// =====================================================================
__global__ __launch_bounds__(256) void k_scan2(
    const float* __restrict__ A_log, const float* __restrict__ Dp)
{
    __shared__ float4 Bsh4[Tc*4];
    __shared__ float4 Csh4[Tc*4];
    float* Bshf = (float*)Bsh4;
    float* Cshf = (float*)Csh4;
    int blk = blockIdx.x;
    int base = blk*Tc;
    int tid = threadIdx.x, lane = tid & 31, wid = tid >> 5;
    for (int t = wid; t < Tc; t += 8) {
        float v = g_dbc[(size_t)(base+t)*40 + 8 + lane];
        if (lane < 16) Bshf[t*16 + lane] = v;
        else           Cshf[t*16 + lane-16] = v;
    }
    __syncthreads();
    int d = tid;
    float a0 = -__expf(A_log[d*DSc]);
    bool uni = true;
    #pragma unroll
    for (int s = 1; s < DSc; ++s) {
        float as = -__expf(A_log[d*DSc+s]);
        uni = uni && (fabsf(as - (float)(s+1)*a0) <= 1e-4f*fabsf((float)(s+1)*a0) + 1e-6f);
    }
    float h[DSc];
    size_t ho = ((size_t)blk*DIc + d)*DSc;
    #pragma unroll
    for (int s = 0; s < DSc; ++s) h[s] = g_hin[ho+s];
    float dp = Dp[d];
    if (uni) {
        #pragma unroll 4
        for (int t = 0; t < Tc; ++t) {
            u32 pk = g_dtx[(size_t)(base+t)*DIc + d];
            float u, e1; UNPACK_DTX(pk, u, e1);
            float x  = __half2float(g_xc[(size_t)(base+t)*DIc + d]);
            float zz = __half2float(g_z[(size_t)(base+t)*DIc + d]);
            float pw[16]; POWER_TREE(pw, e1);
            float4 B0 = Bsh4[t*4+0], B1 = Bsh4[t*4+1], B2 = Bsh4[t*4+2], B3 = Bsh4[t*4+3];
            float4 C0 = Csh4[t*4+0], C1 = Csh4[t*4+1], C2 = Csh4[t*4+2], C3 = Csh4[t*4+3];
            h[0]  = fmaf(pw[0],  h[0],  u*B0.x);
            h[1]  = fmaf(pw[1],  h[1],  u*B0.y);
            h[2]  = fmaf(pw[2],  h[2],  u*B0.z);
            h[3]  = fmaf(pw[3],  h[3],  u*B0.w);
            h[4]  = fmaf(pw[4],  h[4],  u*B1.x);
            h[5]  = fmaf(pw[5],  h[5],  u*B1.y);
            h[6]  = fmaf(pw[6],  h[6],  u*B1.z);
            h[7]  = fmaf(pw[7],  h[7],  u*B1.w);
            h[8]  = fmaf(pw[8],  h[8],  u*B2.x);
            h[9]  = fmaf(pw[9],  h[9],  u*B2.y);
            h[10] = fmaf(pw[10], h[10], u*B2.z);
            h[11] = fmaf(pw[11], h[11], u*B2.w);
            h[12] = fmaf(pw[12], h[12], u*B3.x);
            h[13] = fmaf(pw[13], h[13], u*B3.y);
            h[14] = fmaf(pw[14], h[14], u*B3.z);
            h[15] = fmaf(pw[15], h[15], u*B3.w);
            float y = h[0]*C0.x + h[1]*C0.y + h[2]*C0.z + h[3]*C0.w
                    + h[4]*C1.x + h[5]*C1.y + h[6]*C1.z + h[7]*C1.w
                    + h[8]*C2.x + h[9]*C2.y + h[10]*C2.z + h[11]*C2.w
                    + h[12]*C3.x + h[13]*C3.y + h[14]*C3.z + h[15]*C3.w;
            float sil = zz / (1.f + __expf(-zz));
            g_y[(size_t)(base+t)*DIc + d] = __float2half_rn((y + x*dp)*sil);
        }
    } else {
        #pragma unroll 2
        for (int t = 0; t < Tc; ++t) {
            u32 pk = g_dtx[(size_t)(base+t)*DIc + d];
            float u, e1; UNPACK_DTX(pk, u, e1);
            float x  = __half2float(g_xc[(size_t)(base+t)*DIc + d]);
            float zz = __half2float(g_z[(size_t)(base+t)*DIc + d]);
            float le = __logf(fmaxf(e1, 1e-30f));
            float y = 0.f;
            #pragma unroll
            for (int s = 0; s < DSc; ++s) {
                float as = -__expf(A_log[d*DSc+s]);
                h[s] = __expf(le*(as/a0))*h[s] + u*Bshf[t*16+s];
                y += h[s]*Cshf[t*16+s];
            }
            float sil = zz / (1.f + __expf(-zz));
            g_y[(size_t)(base+t)*DIc + d] = __float2half_rn((y + x*dp)*sil);
        }
    }
}

// =====================================================================
// K7: out_proj (fp16 HMMA, M128, N=128, K=256) + fused LayerNorm + scatter
// =====================================================================
__global__ __launch_bounds__(256) void k_out(
    const int* __restrict__ perm, const float* __restrict__ ln_w,
    const float* __restrict__ ln_b, float* __restrict__ out)
{
    extern __shared__ __half sm[];
    __half *A = sm, *Bh = sm + 128*LDA, *Bl = Bh + 64*LDA;
    float* Cs = (float*)sm;             // overlay after compute
    const u32 A_u = smem_u32(A), Bh_u = smem_u32(Bh), Bl_u = smem_u32(Bl);
    const int tid = threadIdx.x, lane = tid & 31, wid = tid >> 5;
    const int m0 = blockIdx.x * 128;
    const int wm = wid >> 1, wn = wid & 1;

    float acc[2][8][4] = {};
    for (int kc = 0; kc < 2; ++kc) {
        int kk = kc*128;
        for (int i = tid; i < 128*64; i += 256) {
            int r = i >> 6, p = i & 63;
            *(u32*)&A[r*LDA + 2*p] = ((const u32*)g_y)[(size_t)(m0+r)*128 + (kk>>1) + p];
        }
        for (int kb = 0; kb < 2; ++kb) {
            for (int i = tid; i < 64*64; i += 256) {
                int k = i >> 6, p = i & 63;
                *(u32*)&Bh[k*LDA + 2*p] = ((const u32*)g_wout_h)[(kk+kb*64+k)*64 + p];
                *(u32*)&Bl[k*LDA + 2*p] = ((const u32*)g_wout_l)[(kk+kb*64+k)*64 + p];
            }
            __syncthreads();
            #pragma unroll
            for (int k0 = 0; k0 < 64; k0 += 16) {
                u32 a[2][4];
                #pragma unroll
                for (int mf = 0; mf < 2; ++mf)
                    LDSM4(a[mf], A_u + (u32)(((wm*32 + mf*16 + (lane & 15))*LDA
                                              + kb*64 + k0 + (lane >> 4)*8) * 2));
                #pragma unroll
                for (int pass = 0; pass < 2; ++pass) {
                    u32 B_u = pass ? Bl_u : Bh_u;
                    u32 b[8][2];
                    #pragma unroll
                    for (int nf2 = 0; nf2 < 4; ++nf2) {
                        u32 bb[4];
                        LDSM4T(bb, B_u + (u32)(((k0 + (lane & 15))*LDA
                                                + wn*64 + nf2*16 + (lane >> 4)*8) * 2));
                        b[2*nf2+0][0] = bb[0]; b[2*nf2+0][1] = bb[1];
                        b[2*nf2+1][0] = bb[2]; b[2*nf2+1][1] = bb[3];
                    }
                    #pragma unroll
                    for (int mf = 0; mf < 2; ++mf)
                        #pragma unroll
                        for (int nf = 0; nf < 8; ++nf)
                            MMA(acc[mf][nf], a[mf], b[nf]);
                }
            }
            __syncthreads();
        }
    }

    #pragma unroll
    for (int mf = 0; mf < 2; ++mf) {
        int r0 = wm*32 + mf*16 + (lane >> 2);
        #pragma unroll
        for (int nf = 0; nf < 8; ++nf) {
            int ncol = wn*64 + nf*8 + (lane & 3)*2;
            *(float2*)&Cs[r0*132 + ncol]     = make_float2(acc[mf][nf][0], acc[mf][nf][1]);
            *(float2*)&Cs[(r0+8)*132 + ncol] = make_float2(acc[mf][nf][2], acc[mf][nf][3]);
        }
    }
    __syncthreads();

    for (int rr = 0; rr < 16; ++rr) {
        int row = wid*16 + rr;
        float4 v4 = *(float4*)&Cs[row*132 + lane*4];
        float v[4] = {v4.x, v4.y, v4.z, v4.w};
        float sum = 0.f, ssq = 0.f;
        #pragma unroll
        for (int j = 0; j < 4; ++j) { sum += v[j]; ssq += v[j]*v[j]; }
        #pragma unroll
        for (int o = 16; o > 0; o >>= 1) {
            sum += __shfl_xor_sync(0xffffffffu, sum, o);
            ssq += __shfl_xor_sync(0xffffffffu, ssq, o);
        }
        float mu  = sum * (1.f/Dc);
        float var = ssq * (1.f/Dc) - mu*mu;
        float rs  = rsqrtf(var + EPSc);
        int m = m0 + row;
        int dst = (m & ~(Lc-1)) + perm[m];
        int c = lane*4;
        float4 o4;
        o4.x = (v[0]-mu)*rs*ln_w[c+0] + ln_b[c+0];
        o4.y = (v[1]-mu)*rs*ln_w[c+1] + ln_b[c+1];
        o4.z = (v[2]-mu)*rs*ln_w[c+2] + ln_b[c+2];
        o4.w = (v[3]-mu)*rs*ln_w[c+3] + ln_b[c+3];
        *(float4*)(out + (size_t)dst*Dc + c) = o4;
    }
}

// =====================================================================
extern "C" void kernel_launch(void* const* d_in, const int* in_sizes, int n_in,
                              void* d_out, int out_size)
{
    const float* feats      = (const float*)d_in[0];
    const float* pos_w      = (const float*)d_in[1];
    const float* pos_b      = (const float*)d_in[2];
    const float* rms_w      = (const float*)d_in[3];
    const float* in_proj_w  = (const float*)d_in[4];
    const float* conv_w     = (const float*)d_in[5];
    const float* conv_b     = (const float*)d_in[6];
    const float* x_proj_w   = (const float*)d_in[7];
    const float* dt_proj_w  = (const float*)d_in[8];
    const float* dt_proj_b  = (const float*)d_in[9];
    const float* A_log      = (const float*)d_in[10];
    const float* D_param    = (const float*)d_in[11];
    const float* out_proj_w = (const float*)d_in[12];
    const float* ln_w       = (const float*)d_in[13];
    const float* ln_b       = (const float*)d_in[14];
    const int*   coords     = (const int*)  d_in[15];
    const int*   perm       = (const int*)  d_in[16];
    float* out = (float*)d_out;

    const int SM_IN  = (128*LDA + 2*64*LDA)*2;            // 69632
    const int SM_XP  = (128*LDA + 2*128*LDB2)*2;          // 71680
    const int SM_OUT = (128*LDA + 2*64*LDA)*2;            // 69632
    cudaFuncSetAttribute(k_in,  cudaFuncAttributeMaxDynamicSharedMemorySize, SM_IN);
    cudaFuncSetAttribute(k_xp,  cudaFuncAttributeMaxDynamicSharedMemorySize, SM_XP);
    cudaFuncSetAttribute(k_out, cudaFuncAttributeMaxDynamicSharedMemorySize, SM_OUT);

    k_prep <<<(128*512 + 256*128 + 256*64)/256, 256>>>(in_proj_w, out_proj_w, x_proj_w);
    k_in   <<<Nc/128, 256, SM_IN>>>(feats, coords, pos_w, pos_b, rms_w, perm);
    k_xp   <<<Nc/128, 256, SM_XP>>>(conv_w, conv_b);
    k_dt   <<<Bc*NCH, 256>>>(dt_proj_w, dt_proj_b, A_log);
    k_scan1<<<Bc*NCH, 256>>>(A_log);
    k_comb <<<(Bc*DIc*DSc)/(8*32), 256>>>(A_log);
    k_scan2<<<Bc*NCH, 256>>>(A_log, D_param);
    k_out  <<<Nc/128, 256, SM_OUT>>>(perm, ln_w, ln_b, out);
}

// round 16
// speedup vs baseline: 1.0327x; 1.0327x over previous
#include <cuda_runtime.h>
#include <cuda_fp16.h>
#include <math.h>

// Problem constants
#define Bc   4
#define Lc   16384
#define Dc   128
#define DIc  256
#define DSc  16
#define DTRc 8
#define Kc   4
#define Nc   (Bc*Lc)
#define NCH  256
#define Tc   (Lc/NCH)      // 64
#define EPSc 1e-5f

typedef unsigned int       u32;
typedef unsigned short     u16;

// ---------------- scratch (device globals; no allocations) ----------------
__device__ __half  g_xi [Nc*DIc];
__device__ __half  g_z  [Nc*DIc];
__device__ __half  g_xc [Nc*DIc];
__device__ __half  g_y  [Nc*DIc];
__device__ u32     g_dtx[Nc*DIc];     // lo16: u=dt*xc fp16, hi16: e1=exp(dt*a0) fixed *65535
__device__ float   g_dbc[Nc*40];
__device__ float   g_ch [Bc*NCH*DIc*DSc];
__device__ float   g_sdt[Bc*NCH*DIc];
__device__ float   g_hin[Bc*NCH*DIc*DSc];
// fp16 hi/lo split weights, natural [k][n] orientation
__device__ __half g_win_h [128*512], g_win_l [128*512];
__device__ __half g_wout_h[256*128], g_wout_l[256*128];
__device__ __half g_wxp_h [256*64],  g_wxp_l [256*64];

// ---------------- helpers ----------------
__device__ __forceinline__ u32 smem_u32(const void* p) {
    u32 a;
    asm("{ .reg .u64 t; cvta.to.shared.u64 t, %1; cvt.u32.u64 %0, t; }"
        : "=r"(a) : "l"(p));
    return a;
}
__device__ __forceinline__ u32 f2h2(float x, float y) {
    __half2 t = __floats2half2_rn(x, y);
    return *(u32*)&t;
}
#define LDSM4(r, a) \
    asm volatile("ldmatrix.sync.aligned.m8n8.x4.shared.b16 {%0,%1,%2,%3}, [%4];" \
        : "=r"((r)[0]),"=r"((r)[1]),"=r"((r)[2]),"=r"((r)[3]) : "r"(a))
#define LDSM4T(r, a) \
    asm volatile("ldmatrix.sync.aligned.m8n8.x4.trans.shared.b16 {%0,%1,%2,%3}, [%4];" \
        : "=r"((r)[0]),"=r"((r)[1]),"=r"((r)[2]),"=r"((r)[3]) : "r"(a))
#define MMA(c, a, b) \
    asm volatile("mma.sync.aligned.m16n8k16.row.col.f32.f16.f16.f32 " \
        "{%0,%1,%2,%3}, {%4,%5,%6,%7}, {%8,%9}, {%0,%1,%2,%3};" \
        : "+f"((c)[0]),"+f"((c)[1]),"+f"((c)[2]),"+f"((c)[3]) \
        : "r"((a)[0]),"r"((a)[1]),"r"((a)[2]),"r"((a)[3]),"r"((b)[0]),"r"((b)[1]))

#define LDA 136   // smem row stride in halves (272B -> conflict-free ldmatrix)
#define LDB2 72   // x_proj B stride (144B -> conflict-free)

// =====================================================================
// K0: weight prep — fp16 hi/lo split
// =====================================================================
__global__ __launch_bounds__(256) void k_prep(
    const float* __restrict__ inw, const float* __restrict__ outw,
    const float* __restrict__ xpw)
{
    int idx = blockIdx.x*256 + threadIdx.x;
    float v; __half* dh; __half* dl; int slot;
    if (idx < 128*512) {
        v = inw[idx]; dh = g_win_h; dl = g_win_l; slot = idx;
    } else if (idx < 128*512 + 256*128) {
        int i = idx - 128*512;
        v = outw[i]; dh = g_wout_h; dl = g_wout_l; slot = i;
    } else if (idx < 128*512 + 256*128 + 256*64) {
        int i = idx - 128*512 - 256*128;
        int k = i >> 6, n = i & 63;
        v = (n < 40) ? xpw[k*40 + n] : 0.f;
        dh = g_wxp_h; dl = g_wxp_l; slot = i;
    } else return;
    __half h = __float2half_rn(v);
    dh[slot] = h;
    dl[slot] = __float2half_rn(v - __half2float(h));
}

// =====================================================================
// K1: fused embed + gather + RMSNorm + in_proj (fp16 HMMA, M128, N512, K128)
// =====================================================================
__global__ __launch_bounds__(256) void k_in(
    const float* __restrict__ feats, const int* __restrict__ coords,
    const float* __restrict__ pos_w, const float* __restrict__ pos_b,
    const float* __restrict__ rms_w, const int* __restrict__ perm)
{
    extern __shared__ __half sm[];
    __half *A = sm, *Bh = sm + 128*LDA, *Bl = Bh + 64*LDA;
    const u32 A_u = smem_u32(A), Bh_u = smem_u32(Bh), Bl_u = smem_u32(Bl);
    const int tid = threadIdx.x, lane = tid & 31, wid = tid >> 5;
    const int m0 = blockIdx.x * 128;
    const int wm = wid >> 1, wn = wid & 1;

    for (int r = wid; r < 128; r += 8) {
        int m   = m0 + r;
        int src = (m & ~(Lc-1)) + perm[m];
        float c0 = (float)coords[src*3+0];
        float c1 = (float)coords[src*3+1];
        float c2 = (float)coords[src*3+2];
        int c = lane*4;
        float4 f = *(const float4*)(feats + (size_t)src*Dc + c);
        float v[4]; float ss = 0.f;
        #pragma unroll
        for (int j = 0; j < 4; ++j) {
            v[j] = (&f.x)[j] + c0*pos_w[c+j] + c1*pos_w[Dc+c+j]
                   + c2*pos_w[2*Dc+c+j] + pos_b[c+j];
            ss += v[j]*v[j];
        }
        #pragma unroll
        for (int o = 16; o > 0; o >>= 1) ss += __shfl_xor_sync(0xffffffffu, ss, o);
        float rs = rsqrtf(ss*(1.f/Dc) + EPSc);
        int base = r*LDA + c;
        *(u32*)&A[base]   = f2h2(v[0]*rs*rms_w[c+0], v[1]*rs*rms_w[c+1]);
        *(u32*)&A[base+2] = f2h2(v[2]*rs*rms_w[c+2], v[3]*rs*rms_w[c+3]);
    }
    __syncthreads();

    for (int nb = 0; nb < 4; ++nb) {
        float acc[2][8][4] = {};
        for (int kb = 0; kb < 2; ++kb) {
            for (int i = tid; i < 64*64; i += 256) {
                int k = i >> 6, p = i & 63;
                *(u32*)&Bh[k*LDA + 2*p] = ((const u32*)g_win_h)[(kb*64+k)*256 + nb*64 + p];
                *(u32*)&Bl[k*LDA + 2*p] = ((const u32*)g_win_l)[(kb*64+k)*256 + nb*64 + p];
            }
            __syncthreads();
            #pragma unroll
            for (int k0 = 0; k0 < 64; k0 += 16) {
                u32 a[2][4];
                #pragma unroll
                for (int mf = 0; mf < 2; ++mf)
                    LDSM4(a[mf], A_u + (u32)(((wm*32 + mf*16 + (lane & 15))*LDA
                                              + kb*64 + k0 + (lane >> 4)*8) * 2));
                #pragma unroll
                for (int pass = 0; pass < 2; ++pass) {
                    u32 B_u = pass ? Bl_u : Bh_u;
                    u32 b[8][2];
                    #pragma unroll
                    for (int nf2 = 0; nf2 < 4; ++nf2) {
                        u32 bb[4];
                        LDSM4T(bb, B_u + (u32)(((k0 + (lane & 15))*LDA
                                                + wn*64 + nf2*16 + (lane >> 4)*8) * 2));
                        b[2*nf2+0][0] = bb[0]; b[2*nf2+0][1] = bb[1];
                        b[2*nf2+1][0] = bb[2]; b[2*nf2+1][1] = bb[3];
                    }
                    #pragma unroll
                    for (int mf = 0; mf < 2; ++mf)
                        #pragma unroll
                        for (int nf = 0; nf < 8; ++nf)
                            MMA(acc[mf][nf], a[mf], b[nf]);
                }
            }
            __syncthreads();
        }
        __half* dst = (nb < 2) ? g_xi : g_z;
        int nbase = (nb & 1)*128 + wn*64;
        #pragma unroll
        for (int mf = 0; mf < 2; ++mf) {
            int r0 = m0 + wm*32 + mf*16 + (lane >> 2);
            #pragma unroll
            for (int nf = 0; nf < 8; ++nf) {
                int ncol = nbase + nf*8 + (lane & 3)*2;
                *(u32*)&dst[(size_t)r0*DIc + ncol]     = f2h2(acc[mf][nf][0], acc[mf][nf][1]);
                *(u32*)&dst[(size_t)(r0+8)*DIc + ncol] = f2h2(acc[mf][nf][2], acc[mf][nf][3]);
            }
        }
    }
}

// =====================================================================
// K2: fused conv+silu + x_proj (fp16 HMMA, M128, N=64(pad of 40), K=256)
// =====================================================================
__global__ __launch_bounds__(256) void k_xp(
    const float* __restrict__ cw, const float* __restrict__ cb)
{
    extern __shared__ __half sm[];
    __half *A = sm, *Bh = sm + 128*LDA, *Bl = Bh + 128*LDB2;
    const u32 A_u = smem_u32(A), Bh_u = smem_u32(Bh), Bl_u = smem_u32(Bl);
    const int tid = threadIdx.x, lane = tid & 31, wid = tid >> 5;
    const int m0 = blockIdx.x * 128;
    const int wm = wid >> 1, wn = wid & 1;

    float acc[2][4][4] = {};
    for (int kc = 0; kc < 2; ++kc) {
        int kk = kc*128;
        for (int i = tid; i < 128*64; i += 256) {
            int r = i >> 6, p = i & 63;
            int col = kk + 2*p;
            int m = m0 + r;
            float ax = cb[col], ay = cb[col+1];
            #pragma unroll
            for (int j = 0; j < Kc; ++j) {
                if (((m & (Lc-1)) - 3 + j) >= 0) {
                    __half2 xv = *(const __half2*)(g_xi + (size_t)(m-3+j)*DIc + col);
                    float2 xf = __half22float2(xv);
                    ax += xf.x * cw[col*Kc + j];
                    ay += xf.y * cw[(col+1)*Kc + j];
                }
            }
            ax = ax / (1.f + __expf(-ax));
            ay = ay / (1.f + __expf(-ay));
            u32 pk = f2h2(ax, ay);
            *(u32*)(g_xc + (size_t)m*DIc + col) = pk;
            *(u32*)&A[r*LDA + 2*p] = pk;
        }
        for (int i = tid; i < 128*32; i += 256) {
            int k = i >> 5, p = i & 31;
            *(u32*)&Bh[k*LDB2 + 2*p] = ((const u32*)g_wxp_h)[(kk+k)*32 + p];
            *(u32*)&Bl[k*LDB2 + 2*p] = ((const u32*)g_wxp_l)[(kk+k)*32 + p];
        }
        __syncthreads();

        #pragma unroll
        for (int k0 = 0; k0 < 128; k0 += 16) {
            u32 a[2][4];
            #pragma unroll
            for (int mf = 0; mf < 2; ++mf)
                LDSM4(a[mf], A_u + (u32)(((wm*32 + mf*16 + (lane & 15))*LDA
                                          + k0 + (lane >> 4)*8) * 2));
            #pragma unroll
            for (int pass = 0; pass < 2; ++pass) {
                u32 B_u = pass ? Bl_u : Bh_u;
                u32 b[4][2];
                #pragma unroll
                for (int nf2 = 0; nf2 < 2; ++nf2) {
                    u32 bb[4];
                    LDSM4T(bb, B_u + (u32)(((k0 + (lane & 15))*LDB2
                                            + wn*32 + nf2*16 + (lane >> 4)*8) * 2));
                    b[2*nf2+0][0] = bb[0]; b[2*nf2+0][1] = bb[1];
                    b[2*nf2+1][0] = bb[2]; b[2*nf2+1][1] = bb[3];
                }
                #pragma unroll
                for (int mf = 0; mf < 2; ++mf)
                    #pragma unroll
                    for (int nf = 0; nf < 4; ++nf)
                        MMA(acc[mf][nf], a[mf], b[nf]);
            }
        }
        __syncthreads();
    }

    #pragma unroll
    for (int mf = 0; mf < 2; ++mf) {
        int r0 = m0 + wm*32 + mf*16 + (lane >> 2);
        #pragma unroll
        for (int nf = 0; nf < 4; ++nf) {
            int ncol = wn*32 + nf*8 + (lane & 3)*2;
            if (ncol < 40) {
                *(float2*)&g_dbc[(size_t)r0*40 + ncol]     = make_float2(acc[mf][nf][0], acc[mf][nf][1]);
                *(float2*)&g_dbc[(size_t)(r0+8)*40 + ncol] = make_float2(acc[mf][nf][2], acc[mf][nf][3]);
            }
        }
    }
}

// ---------------- power tree: pw[s] = e1^(s+1), depth ~3 ----------------
#define POWER_TREE(pw, e1) do { \
    float _e2 = (e1)*(e1), _e4 = _e2*_e2, _e8 = _e4*_e4; \
    pw[0]=(e1); pw[1]=_e2; pw[2]=_e2*(e1); pw[3]=_e4; \
    pw[4]=_e4*(e1); pw[5]=_e4*_e2; pw[6]=_e4*pw[2]; pw[7]=_e8; \
    pw[8]=_e8*(e1); pw[9]=_e8*_e2; pw[10]=_e8*pw[2]; pw[11]=_e8*_e4; \
    pw[12]=_e8*pw[4]; pw[13]=_e8*pw[5]; pw[14]=_e8*pw[6]; pw[15]=_e8*_e8; \
} while (0)

#define UNPACK_DTX(pk, u, e1) do { \
    (u)  = __half2float(__ushort_as_half((u16)((pk) & 0xFFFFu))); \
    (e1) = (float)((pk) >> 16) * (1.f/65535.f); \
} while (0)

// =====================================================================
// K3: FUSED dt + scan pass 1.
//     Computes dt=softplus(dt8@W+b), packs (u,e1) -> g_dtx, sums dt,
//     and runs the chunk-local h recurrence using the SAME quantized
//     values (bit-identical to the old separate scan1). Emits g_ch, g_sdt.
// =====================================================================
__global__ __launch_bounds__(256) void k_dts1(
    const float* __restrict__ dtw, const float* __restrict__ dtb,
    const float* __restrict__ A_log)
{
    __shared__ float dr[Tc][8];
    __shared__ float4 Bsh4[Tc*4];
    float* Bshf = (float*)Bsh4;
    int blk = blockIdx.x;          // = b*NCH + ch
    int m0 = blk*Tc;
    int tid = threadIdx.x, lane = tid & 31, wid = tid >> 5;
    { int t = tid >> 2, k2 = (tid & 3)*2;
      *(float2*)&dr[t][k2] = *(const float2*)&g_dbc[(size_t)(m0+t)*40 + k2]; }
    for (int t = wid; t < Tc; t += 8)
        if (lane < 16) Bshf[t*16 + lane] = g_dbc[(size_t)(m0+t)*40 + 8 + lane];
    __syncthreads();

    int d = tid;
    float wr[8];
    #pragma unroll
    for (int k = 0; k < 8; ++k) wr[k] = dtw[k*DIc + d];
    float b = dtb[d];
    float a0 = -__expf(A_log[d*DSc]);
    bool uni = true;
    #pragma unroll
    for (int s = 1; s < DSc; ++s) {
        float as = -__expf(A_log[d*DSc+s]);
        uni = uni && (fabsf(as - (float)(s+1)*a0) <= 1e-4f*fabsf((float)(s+1)*a0) + 1e-6f);
    }
    float h[DSc];
    #pragma unroll
    for (int s = 0; s < DSc; ++s) h[s] = 0.f;
    float sdt = 0.f;

    if (uni) {
        #pragma unroll 2
        for (int t = 0; t < Tc; ++t) {
            float v = b;
            #pragma unroll
            for (int k = 0; k < 8; ++k) v += dr[t][k]*wr[k];
            float sp = (v > 15.f) ? v : __logf(1.f + __expf(v));
            sdt += sp;
            float xcv = __half2float(g_xc[(size_t)(m0+t)*DIc + d]);
            float e1f = __expf(sp * a0);
            u32 pk = (u32)__half_as_ushort(__float2half_rn(sp * xcv))
                   | ((u32)(int)(e1f*65535.f + 0.5f) << 16);
            g_dtx[(size_t)(m0+t)*DIc + d] = pk;
            float u, e1; UNPACK_DTX(pk, u, e1);
            float pw[16]; POWER_TREE(pw, e1);
            float4 B0 = Bsh4[t*4+0], B1 = Bsh4[t*4+1], B2 = Bsh4[t*4+2], B3 = Bsh4[t*4+3];
            h[0]  = fmaf(pw[0],  h[0],  u*B0.x);
            h[1]  = fmaf(pw[1],  h[1],  u*B0.y);
            h[2]  = fmaf(pw[2],  h[2],  u*B0.z);
            h[3]  = fmaf(pw[3],  h[3],  u*B0.w);
            h[4]  = fmaf(pw[4],  h[4],  u*B1.x);
            h[5]  = fmaf(pw[5],  h[5],  u*B1.y);
            h[6]  = fmaf(pw[6],  h[6],  u*B1.z);
            h[7]  = fmaf(pw[7],  h[7],  u*B1.w);
            h[8]  = fmaf(pw[8],  h[8],  u*B2.x);
            h[9]  = fmaf(pw[9],  h[9],  u*B2.y);
            h[10] = fmaf(pw[10], h[10], u*B2.z);
            h[11] = fmaf(pw[11], h[11], u*B2.w);
            h[12] = fmaf(pw[12], h[12], u*B3.x);
            h[13] = fmaf(pw[13], h[13], u*B3.y);
            h[14] = fmaf(pw[14], h[14], u*B3.z);
            h[15] = fmaf(pw[15], h[15], u*B3.w);
        }
    } else {
        #pragma unroll 2
        for (int t = 0; t < Tc; ++t) {
            float v = b;
            #pragma unroll
            for (int k = 0; k < 8; ++k) v += dr[t][k]*wr[k];
            float sp = (v > 15.f) ? v : __logf(1.f + __expf(v));
            sdt += sp;
            float xcv = __half2float(g_xc[(size_t)(m0+t)*DIc + d]);
            float e1f = __expf(sp * a0);
            u32 pk = (u32)__half_as_ushort(__float2half_rn(sp * xcv))
                   | ((u32)(int)(e1f*65535.f + 0.5f) << 16);
            g_dtx[(size_t)(m0+t)*DIc + d] = pk;
            float u, e1; UNPACK_DTX(pk, u, e1);
            float le = __logf(fmaxf(e1, 1e-30f));    // = dt*a0 (quantized)
            #pragma unroll
            for (int s = 0; s < DSc; ++s) {
                float as = -__expf(A_log[d*DSc+s]);
                h[s] = __expf(le*(as/a0))*h[s] + u*Bshf[t*16+s];
            }
        }
    }
    size_t co = ((size_t)blk*DIc + d)*DSc;
    #pragma unroll
    for (int s = 0; s < DSc; ++s) g_ch[co+s] = h[s];
    g_sdt[(size_t)blk*DIc + d] = sdt;
}

// =====================================================================
// K5: chunk combine — warp-parallel affine scan (one warp per (b,d,s))
// =====================================================================
__global__ __launch_bounds__(256) void k_comb(const float* __restrict__ A_log)
{
    int sid = blockIdx.x*8 + (threadIdx.x >> 5);   // series id < 16384
    int lane = threadIdx.x & 31;
    int b = sid >> 12;
    int d = (sid >> 4) & (DIc-1);
    int s = sid & 15;
    float a = -__expf(A_log[d*DSc + s]);

    float dec[8], cv[8];
    int ch0 = lane*8;
    #pragma unroll
    for (int j = 0; j < 8; ++j) {
        int ch = ch0 + j;
        cv[j]  = g_ch[((size_t)(b*NCH+ch)*DIc + d)*DSc + s];
        dec[j] = __expf(a * g_sdt[(size_t)(b*NCH+ch)*DIc + d]);
    }
    float P = 1.f, S = 0.f;
    #pragma unroll
    for (int j = 0; j < 8; ++j) { S = dec[j]*S + cv[j]; P *= dec[j]; }
    #pragma unroll
    for (int o = 1; o < 32; o <<= 1) {
        float Pp = __shfl_up_sync(0xffffffffu, P, o);
        float Sp = __shfl_up_sync(0xffffffffu, S, o);
        if (lane >= o) { S = fmaf(P, Sp, S); P *= Pp; }
    }
    float H = __shfl_up_sync(0xffffffffu, S, 1);
    if (lane == 0) H = 0.f;
    #pragma unroll
    for (int j = 0; j < 8; ++j) {
        int ch = ch0 + j;
        g_hin[((size_t)(b*NCH+ch)*DIc + d)*DSc + s] = H;
        H = dec[j]*H + cv[j];
    }
}

// =====================================================================
// K6: scan pass 2 — replay with carry-in + fused +xc*D and *silu(z)
// =====================================================================
__global__ __launch_bounds__(256) void k_scan2(
    const float* __restrict__ A_log, const float* __restrict__ Dp)
{
    __shared__ float4 Bsh4[Tc*4];
    __shared__ float4 Csh4[Tc*4];
    float* Bshf = (float*)Bsh4;
    float* Cshf = (float*)Csh4;
    int blk = blockIdx.x;
    int base = blk*Tc;
    int tid = threadIdx.x, lane = tid & 31, wid = tid >> 5;
    for (int t = wid; t < Tc; t += 8) {
        float v = g_dbc[(size_t)(base+t)*40 + 8 + lane];
        if (lane < 16) Bshf[t*16 + lane] = v;
        else           Cshf[t*16 + lane-16] = v;
    }
    __syncthreads();
    int d = tid;
    float a0 = -__expf(A_log[d*DSc]);
    bool uni = true;
    #pragma unroll
    for (int s = 1; s < DSc; ++s) {
        float as = -__expf(A_log[d*DSc+s]);
        uni = uni && (fabsf(as - (float)(s+1)*a0) <= 1e-4f*fabsf((float)(s+1)*a0) + 1e-6f);
    }
    float h[DSc];
    size_t ho = ((size_t)blk*DIc + d)*DSc;
    #pragma unroll
    for (int s = 0; s < DSc; ++s) h[s] = g_hin[ho+s];
    float dp = Dp[d];
    if (uni) {
        #pragma unroll 4
        for (int t = 0; t < Tc; ++t) {
            u32 pk = g_dtx[(size_t)(base+t)*DIc + d];
            float u, e1; UNPACK_DTX(pk, u, e1);
            float x  = __half2float(g_xc[(size_t)(base+t)*DIc + d]);
            float zz = __half2float(g_z[(size_t)(base+t)*DIc + d]);
            float pw[16]; POWER_TREE(pw, e1);
            float4 B0 = Bsh4[t*4+0], B1 = Bsh4[t*4+1], B2 = Bsh4[t*4+2], B3 = Bsh4[t*4+3];
            float4 C0 = Csh4[t*4+0], C1 = Csh4[t*4+1], C2 = Csh4[t*4+2], C3 = Csh4[t*4+3];
            h[0]  = fmaf(pw[0],  h[0],  u*B0.x);
            h[1]  = fmaf(pw[1],  h[1],  u*B0.y);
            h[2]  = fmaf(pw[2],  h[2],  u*B0.z);
            h[3]  = fmaf(pw[3],  h[3],  u*B0.w);
            h[4]  = fmaf(pw[4],  h[4],  u*B1.x);
            h[5]  = fmaf(pw[5],  h[5],  u*B1.y);
            h[6]  = fmaf(pw[6],  h[6],  u*B1.z);
            h[7]  = fmaf(pw[7],  h[7],  u*B1.w);
            h[8]  = fmaf(pw[8],  h[8],  u*B2.x);
            h[9]  = fmaf(pw[9],  h[9],  u*B2.y);
            h[10] = fmaf(pw[10], h[10], u*B2.z);
            h[11] = fmaf(pw[11], h[11], u*B2.w);
            h[12] = fmaf(pw[12], h[12], u*B3.x);
            h[13] = fmaf(pw[13], h[13], u*B3.y);
            h[14] = fmaf(pw[14], h[14], u*B3.z);
            h[15] = fmaf(pw[15], h[15], u*B3.w);
            float y = h[0]*C0.x + h[1]*C0.y + h[2]*C0.z + h[3]*C0.w
                    + h[4]*C1.x + h[5]*C1.y + h[6]*C1.z + h[7]*C1.w
                    + h[8]*C2.x + h[9]*C2.y + h[10]*C2.z + h[11]*C2.w
                    + h[12]*C3.x + h[13]*C3.y + h[14]*C3.z + h[15]*C3.w;
            float sil = zz / (1.f + __expf(-zz));
            g_y[(size_t)(base+t)*DIc + d] = __float2half_rn((y + x*dp)*sil);
        }
    } else {
        #pragma unroll 2
        for (int t = 0; t < Tc; ++t) {
            u32 pk = g_dtx[(size_t)(base+t)*DIc + d];
            float u, e1; UNPACK_DTX(pk, u, e1);
            float x  = __half2float(g_xc[(size_t)(base+t)*DIc + d]);
            float zz = __half2float(g_z[(size_t)(base+t)*DIc + d]);
            float le = __logf(fmaxf(e1, 1e-30f));
            float y = 0.f;
            #pragma unroll
            for (int s = 0; s < DSc; ++s) {
                float as = -__expf(A_log[d*DSc+s]);
                h[s] = __expf(le*(as/a0))*h[s] + u*Bshf[t*16+s];
                y += h[s]*Cshf[t*16+s];
            }
            float sil = zz / (1.f + __expf(-zz));
            g_y[(size_t)(base+t)*DIc + d] = __float2half_rn((y + x*dp)*sil);
        }
    }
}

// =====================================================================
// K7: out_proj (fp16 HMMA, M128, N=128, K=256) + fused LayerNorm + scatter
// =====================================================================
__global__ __launch_bounds__(256) void k_out(
    const int* __restrict__ perm, const float* __restrict__ ln_w,
    const float* __restrict__ ln_b, float* __restrict__ out)
{
    extern __shared__ __half sm[];
    __half *A = sm, *Bh = sm + 128*LDA, *Bl = Bh + 64*LDA;
    float* Cs = (float*)sm;             // overlay after compute
    const u32 A_u = smem_u32(A), Bh_u = smem_u32(Bh), Bl_u = smem_u32(Bl);
    const int tid = threadIdx.x, lane = tid & 31, wid = tid >> 5;
    const int m0 = blockIdx.x * 128;
    const int wm = wid >> 1, wn = wid & 1;

    float acc[2][8][4] = {};
    for (int kc = 0; kc < 2; ++kc) {
        int kk = kc*128;
        for (int i = tid; i < 128*64; i += 256) {
            int r = i >> 6, p = i & 63;
            *(u32*)&A[r*LDA + 2*p] = ((const u32*)g_y)[(size_t)(m0+r)*128 + (kk>>1) + p];
        }
        for (int kb = 0; kb < 2; ++kb) {
            for (int i = tid; i < 64*64; i += 256) {
                int k = i >> 6, p = i & 63;
                *(u32*)&Bh[k*LDA + 2*p] = ((const u32*)g_wout_h)[(kk+kb*64+k)*64 + p];
                *(u32*)&Bl[k*LDA + 2*p] = ((const u32*)g_wout_l)[(kk+kb*64+k)*64 + p];
            }
            __syncthreads();
            #pragma unroll
            for (int k0 = 0; k0 < 64; k0 += 16) {
                u32 a[2][4];
                #pragma unroll
                for (int mf = 0; mf < 2; ++mf)
                    LDSM4(a[mf], A_u + (u32)(((wm*32 + mf*16 + (lane & 15))*LDA
                                              + kb*64 + k0 + (lane >> 4)*8) * 2));
                #pragma unroll
                for (int pass = 0; pass < 2; ++pass) {
                    u32 B_u = pass ? Bl_u : Bh_u;
                    u32 b[8][2];
                    #pragma unroll
                    for (int nf2 = 0; nf2 < 4; ++nf2) {
                        u32 bb[4];
                        LDSM4T(bb, B_u + (u32)(((k0 + (lane & 15))*LDA
                                                + wn*64 + nf2*16 + (lane >> 4)*8) * 2));
                        b[2*nf2+0][0] = bb[0]; b[2*nf2+0][1] = bb[1];
                        b[2*nf2+1][0] = bb[2]; b[2*nf2+1][1] = bb[3];
                    }
                    #pragma unroll
                    for (int mf = 0; mf < 2; ++mf)
                        #pragma unroll
                        for (int nf = 0; nf < 8; ++nf)
                            MMA(acc[mf][nf], a[mf], b[nf]);
                }
            }
            __syncthreads();
        }
    }

    #pragma unroll
    for (int mf = 0; mf < 2; ++mf) {
        int r0 = wm*32 + mf*16 + (lane >> 2);
        #pragma unroll
        for (int nf = 0; nf < 8; ++nf) {
            int ncol = wn*64 + nf*8 + (lane & 3)*2;
            *(float2*)&Cs[r0*132 + ncol]     = make_float2(acc[mf][nf][0], acc[mf][nf][1]);
            *(float2*)&Cs[(r0+8)*132 + ncol] = make_float2(acc[mf][nf][2], acc[mf][nf][3]);
        }
    }
    __syncthreads();

    for (int rr = 0; rr < 16; ++rr) {
        int row = wid*16 + rr;
        float4 v4 = *(float4*)&Cs[row*132 + lane*4];
        float v[4] = {v4.x, v4.y, v4.z, v4.w};
        float sum = 0.f, ssq = 0.f;
        #pragma unroll
        for (int j = 0; j < 4; ++j) { sum += v[j]; ssq += v[j]*v[j]; }
        #pragma unroll
        for (int o = 16; o > 0; o >>= 1) {
            sum += __shfl_xor_sync(0xffffffffu, sum, o);
            ssq += __shfl_xor_sync(0xffffffffu, ssq, o);
        }
        float mu  = sum * (1.f/Dc);
        float var = ssq * (1.f/Dc) - mu*mu;
        float rs  = rsqrtf(var + EPSc);
        int m = m0 + row;
        int dst = (m & ~(Lc-1)) + perm[m];
        int c = lane*4;
        float4 o4;
        o4.x = (v[0]-mu)*rs*ln_w[c+0] + ln_b[c+0];
        o4.y = (v[1]-mu)*rs*ln_w[c+1] + ln_b[c+1];
        o4.z = (v[2]-mu)*rs*ln_w[c+2] + ln_b[c+2];
        o4.w = (v[3]-mu)*rs*ln_w[c+3] + ln_b[c+3];
        *(float4*)(out + (size_t)dst*Dc + c) = o4;
    }
}

// =====================================================================
extern "C" void kernel_launch(void* const* d_in, const int* in_sizes, int n_in,
                              void* d_out, int out_size)
{
    const float* feats      = (const float*)d_in[0];
    const float* pos_w      = (const float*)d_in[1];
    const float* pos_b      = (const float*)d_in[2];
    const float* rms_w      = (const float*)d_in[3];
    const float* in_proj_w  = (const float*)d_in[4];
    const float* conv_w     = (const float*)d_in[5];
    const float* conv_b     = (const float*)d_in[6];
    const float* x_proj_w   = (const float*)d_in[7];
    const float* dt_proj_w  = (const float*)d_in[8];
    const float* dt_proj_b  = (const float*)d_in[9];
    const float* A_log      = (const float*)d_in[10];
    const float* D_param    = (const float*)d_in[11];
    const float* out_proj_w = (const float*)d_in[12];
    const float* ln_w       = (const float*)d_in[13];
    const float* ln_b       = (const float*)d_in[14];
    const int*   coords     = (const int*)  d_in[15];
    const int*   perm       = (const int*)  d_in[16];
    float* out = (float*)d_out;

    const int SM_IN  = (128*LDA + 2*64*LDA)*2;            // 69632
    const int SM_XP  = (128*LDA + 2*128*LDB2)*2;          // 71680
    const int SM_OUT = (128*LDA + 2*64*LDA)*2;            // 69632
    cudaFuncSetAttribute(k_in,  cudaFuncAttributeMaxDynamicSharedMemorySize, SM_IN);
    cudaFuncSetAttribute(k_xp,  cudaFuncAttributeMaxDynamicSharedMemorySize, SM_XP);
    cudaFuncSetAttribute(k_out, cudaFuncAttributeMaxDynamicSharedMemorySize, SM_OUT);

    k_prep <<<(128*512 + 256*128 + 256*64)/256, 256>>>(in_proj_w, out_proj_w, x_proj_w);
    k_in   <<<Nc/128, 256, SM_IN>>>(feats, coords, pos_w, pos_b, rms_w, perm);
    k_xp   <<<Nc/128, 256, SM_XP>>>(conv_w, conv_b);
    k_dts1 <<<Bc*NCH, 256>>>(dt_proj_w, dt_proj_b, A_log);
    k_comb <<<(Bc*DIc*DSc)/(8*32), 256>>>(A_log);
    k_scan2<<<Bc*NCH, 256>>>(A_log, D_param);
    k_out  <<<Nc/128, 256, SM_OUT>>>(perm, ln_w, ln_b, out);
}